// round 9
// baseline (speedup 1.0000x reference)
#include <cuda_runtime.h>
#include <cuda_fp16.h>
#include <math.h>
#include <stdint.h>

#define EMBED   1024
#define HEADS   16
#define HDIM    64
#define BATCH   4
#define TSEQ    2048
#define MROWS   (BATCH * TSEQ)   // 8192

// ================= helpers =================
__device__ __forceinline__ uint32_t smem_u32(const void* p) {
    uint32_t a;
    asm("{ .reg .u64 t; cvta.to.shared.u64 t, %1; cvt.u32.u64 %0, t; }" : "=r"(a) : "l"(p));
    return a;
}
__device__ __forceinline__ uint32_t swz128(uint32_t off) { return off ^ ((off >> 3) & 0x70); }

__device__ __forceinline__ void cp_async16(uint32_t dst, const void* src) {
    asm volatile("cp.async.cg.shared.global [%0], [%1], 16;" :: "r"(dst), "l"(src));
}
#define CP_COMMIT() asm volatile("cp.async.commit_group;" ::: "memory")
#define CP_WAIT(n)  asm volatile("cp.async.wait_group %0;" :: "n"(n) : "memory")

__device__ __forceinline__ void ldsm_x4(uint32_t* r, uint32_t addr) {
    asm volatile("ldmatrix.sync.aligned.m8n8.x4.shared.b16 {%0,%1,%2,%3}, [%4];"
        : "=r"(r[0]), "=r"(r[1]), "=r"(r[2]), "=r"(r[3]) : "r"(addr));
}
__device__ __forceinline__ void ldsm_x4_t(uint32_t* r, uint32_t addr) {
    asm volatile("ldmatrix.sync.aligned.m8n8.x4.trans.shared.b16 {%0,%1,%2,%3}, [%4];"
        : "=r"(r[0]), "=r"(r[1]), "=r"(r[2]), "=r"(r[3]) : "r"(addr));
}
__device__ __forceinline__ void mma16816h(float* d, const uint32_t* a, const uint32_t* b) {
    asm volatile("mma.sync.aligned.m16n8k16.row.col.f32.f16.f16.f32 "
        "{%0,%1,%2,%3}, {%4,%5,%6,%7}, {%8,%9}, {%0,%1,%2,%3};"
        : "+f"(d[0]), "+f"(d[1]), "+f"(d[2]), "+f"(d[3])
        : "r"(a[0]), "r"(a[1]), "r"(a[2]), "r"(a[3]), "r"(b[0]), "r"(b[1]));
}
__device__ __forceinline__ uint32_t pack_h(float x, float y) {
    __half hx = __float2half_rn(x), hy = __float2half_rn(y);
    return (uint32_t)__half_as_ushort(hx) | ((uint32_t)__half_as_ushort(hy) << 16);
}

// ================= scratch (single fp16) =================
__device__ __half g_qh[BATCH * HEADS * TSEQ * HDIM];
__device__ __half g_kh[BATCH * HEADS * TSEQ * HDIM];
__device__ __half g_vh[BATCH * HEADS * TSEQ * HDIM];
__device__ __half g_oh[MROWS * EMBED];
__device__ __half g_xh[MROWS * EMBED];
__device__ __half g_wth[4 * EMBED * EMBED];   // Wt[N,K] per weight

#define QSCALE (0.125f * 1.4426950408889634f)

// ================= cast x -> fp16 =================
__global__ __launch_bounds__(256)
void cast_f32h(const float* __restrict__ in, __half* __restrict__ hi, int n4)
{
    int i = blockIdx.x * blockDim.x + threadIdx.x;
    if (i >= n4) return;
    float4 v = ((const float4*)in)[i];
    ((uint2*)hi)[i] = make_uint2(pack_h(v.x, v.y), pack_h(v.z, v.w));
}

// ================= transpose all 4 weights =================
__global__ __launch_bounds__(256)
void transpose_h4(const float* __restrict__ W0, const float* __restrict__ W1,
                  const float* __restrict__ W2, const float* __restrict__ W3,
                  __half* __restrict__ hi)
{
    __shared__ float t[32][33];
    const int z = blockIdx.z;
    const float* W = (z == 0) ? W0 : (z == 1) ? W1 : (z == 2) ? W2 : W3;
    __half* dst = hi + (size_t)z * EMBED * EMBED;
    const int bx = blockIdx.x * 32;
    const int by = blockIdx.y * 32;
    const int x = threadIdx.x, y = threadIdx.y;
    #pragma unroll
    for (int j = 0; j < 32; j += 8)
        t[y + j][x] = W[(size_t)(by + y + j) * EMBED + bx + x];
    __syncthreads();
    #pragma unroll
    for (int j = 0; j < 32; j += 8)
        dst[(size_t)(bx + y + j) * EMBED + by + x] = __float2half_rn(t[x][y + j]);
}

// ================= single-fp16 HMMA GEMM (3-stage) =================
#define TILE_B  16384     // 128 rows x 64 fp16 x 2B
#define STAGE_B 32768     // 2 tiles: Ah, Bh

__global__ __launch_bounds__(256, 2)
void qkv_gemm(const __half* __restrict__ Ah_, const __half* __restrict__ Wh,
              const float* __restrict__ bq, const float* __restrict__ bk, const float* __restrict__ bv,
              __half* __restrict__ qh, __half* __restrict__ kh, __half* __restrict__ vh)
{
    constexpr int K = EMBED, NK = 16;
    extern __shared__ __align__(1024) char smem[];
    const uint32_t sb = smem_u32(smem);
    const int tid = threadIdx.x, wid = tid >> 5, lane = tid & 31;
    const int widx = blockIdx.x >> 3;
    const int n0 = (blockIdx.x & 7) * 128, m0 = blockIdx.y * 128;
    const size_t WN = (size_t)EMBED * EMBED;

    const __half* Bh = Wh + (size_t)widx * WN;
    const float* bias = (widx == 0) ? bq : (widx == 1) ? bk : bv;
    __half* Cdst = (widx == 0) ? qh : (widx == 1) ? kh : vh;
    const float scale = (widx == 0) ? QSCALE : 1.0f;

    const int warp_m = wid & 3, warp_n = wid >> 2;
    float acc[2][8][4];
    #pragma unroll
    for (int mb = 0; mb < 2; mb++)
        #pragma unroll
        for (int nb = 0; nb < 8; nb++)
            #pragma unroll
            for (int j = 0; j < 4; j++) acc[mb][nb][j] = 0.f;

    const int a_row = warp_m * 32 + (lane & 7) + ((lane >> 3) & 1) * 8;
    const int a_col = (lane >> 4) * 16;
    const int b_row = warp_n * 64 + (lane & 7) + (lane >> 4) * 8;
    const int b_col = ((lane >> 3) & 1) * 16;

    const __half* srcs[2] = {Ah_, Bh};

    auto load_chunk = [&](int kt, int s) {
        #pragma unroll
        for (int t = 0; t < 2; t++) {
            const __half* base = srcs[t] + (size_t)((t == 0) ? m0 : n0) * K + kt * 64;
            const uint32_t tb = sb + s * STAGE_B + t * TILE_B;
            #pragma unroll
            for (int i = 0; i < 4; i++) {
                int chunk = tid + i * 256;
                int r = chunk >> 3, c = chunk & 7;
                cp_async16(tb + swz128(r * 128 + c * 16), base + (size_t)r * K + c * 8);
            }
        }
        CP_COMMIT();
    };

    load_chunk(0, 0);
    load_chunk(1, 1);
    for (int kt = 0; kt < NK; kt++) {
        const int st = kt % 3;
        if (kt + 2 < NK)       { load_chunk(kt + 2, (kt + 2) % 3); CP_WAIT(2); }
        else if (kt + 2 == NK) { CP_WAIT(1); }
        else                   { CP_WAIT(0); }
        __syncthreads();
        const uint32_t tAh = sb + st * STAGE_B, tBh = tAh + TILE_B;
        #pragma unroll
        for (int ks = 0; ks < 4; ks++) {
            uint32_t ah[2][4], bh4[4][4];
            #pragma unroll
            for (int mb = 0; mb < 2; mb++)
                ldsm_x4(ah[mb], tAh + swz128((a_row + mb * 16) * 128 + a_col + ks * 32));
            #pragma unroll
            for (int nb = 0; nb < 4; nb++)
                ldsm_x4(bh4[nb], tBh + swz128((b_row + nb * 16) * 128 + b_col + ks * 32));
            #pragma unroll
            for (int mb = 0; mb < 2; mb++)
                #pragma unroll
                for (int nb = 0; nb < 4; nb++)
                    #pragma unroll
                    for (int h = 0; h < 2; h++)
                        mma16816h(acc[mb][nb * 2 + h], ah[mb], &bh4[nb][h * 2]);
        }
        __syncthreads();
    }

    const int er = m0 + warp_m * 32 + (lane >> 2);
    const int ec = n0 + warp_n * 64 + (lane & 3) * 2;
    #pragma unroll
    for (int mb = 0; mb < 2; mb++) {
        #pragma unroll
        for (int half = 0; half < 2; half++) {
            const int row = er + mb * 16 + half * 8;
            const int b = row / TSEQ, t = row % TSEQ;
            #pragma unroll
            for (int nb = 0; nb < 8; nb++) {
                const int col = ec + nb * 8;
                const float v0 = (acc[mb][nb][half * 2 + 0] + bias[col]) * scale;
                const float v1 = (acc[mb][nb][half * 2 + 1] + bias[col + 1]) * scale;
                const int hh = col >> 6, dd = col & 63;
                const size_t idx = (((size_t)(b * HEADS + hh)) * TSEQ + t) * HDIM + dd;
                *(uint32_t*)(Cdst + idx) = pack_h(v0, v1);
            }
        }
    }
}

__global__ __launch_bounds__(256, 2)
void out_gemm(const __half* __restrict__ Ah_, const __half* __restrict__ Bh_,
              const float* __restrict__ bias, float* __restrict__ Cf)
{
    constexpr int K = EMBED, NG = EMBED, NK = 16;
    extern __shared__ __align__(1024) char smem[];
    const uint32_t sb = smem_u32(smem);
    const int tid = threadIdx.x, wid = tid >> 5, lane = tid & 31;
    const int n0 = blockIdx.x * 128, m0 = blockIdx.y * 128;

    const int warp_m = wid & 3, warp_n = wid >> 2;
    float acc[2][8][4];
    #pragma unroll
    for (int mb = 0; mb < 2; mb++)
        #pragma unroll
        for (int nb = 0; nb < 8; nb++)
            #pragma unroll
            for (int j = 0; j < 4; j++) acc[mb][nb][j] = 0.f;

    const int a_row = warp_m * 32 + (lane & 7) + ((lane >> 3) & 1) * 8;
    const int a_col = (lane >> 4) * 16;
    const int b_row = warp_n * 64 + (lane & 7) + (lane >> 4) * 8;
    const int b_col = ((lane >> 3) & 1) * 16;

    const __half* srcs[2] = {Ah_, Bh_};

    auto load_chunk = [&](int kt, int s) {
        #pragma unroll
        for (int t = 0; t < 2; t++) {
            const __half* base = srcs[t] + (size_t)((t == 0) ? m0 : n0) * K + kt * 64;
            const uint32_t tb = sb + s * STAGE_B + t * TILE_B;
            #pragma unroll
            for (int i = 0; i < 4; i++) {
                int chunk = tid + i * 256;
                int r = chunk >> 3, c = chunk & 7;
                cp_async16(tb + swz128(r * 128 + c * 16), base + (size_t)r * K + c * 8);
            }
        }
        CP_COMMIT();
    };

    load_chunk(0, 0);
    load_chunk(1, 1);
    for (int kt = 0; kt < NK; kt++) {
        const int st = kt % 3;
        if (kt + 2 < NK)       { load_chunk(kt + 2, (kt + 2) % 3); CP_WAIT(2); }
        else if (kt + 2 == NK) { CP_WAIT(1); }
        else                   { CP_WAIT(0); }
        __syncthreads();
        const uint32_t tAh = sb + st * STAGE_B, tBh = tAh + TILE_B;
        #pragma unroll
        for (int ks = 0; ks < 4; ks++) {
            uint32_t ah[2][4], bh4[4][4];
            #pragma unroll
            for (int mb = 0; mb < 2; mb++)
                ldsm_x4(ah[mb], tAh + swz128((a_row + mb * 16) * 128 + a_col + ks * 32));
            #pragma unroll
            for (int nb = 0; nb < 4; nb++)
                ldsm_x4(bh4[nb], tBh + swz128((b_row + nb * 16) * 128 + b_col + ks * 32));
            #pragma unroll
            for (int mb = 0; mb < 2; mb++)
                #pragma unroll
                for (int nb = 0; nb < 4; nb++)
                    #pragma unroll
                    for (int h = 0; h < 2; h++)
                        mma16816h(acc[mb][nb * 2 + h], ah[mb], &bh4[nb][h * 2]);
        }
        __syncthreads();
    }

    const int er = m0 + warp_m * 32 + (lane >> 2);
    const int ec = n0 + warp_n * 64 + (lane & 3) * 2;
    #pragma unroll
    for (int mb = 0; mb < 2; mb++) {
        #pragma unroll
        for (int half = 0; half < 2; half++) {
            const int row = er + mb * 16 + half * 8;
            #pragma unroll
            for (int nb = 0; nb < 8; nb++) {
                const int col = ec + nb * 8;
                float* dst = Cf + (size_t)row * NG + col;
                dst[0] = acc[mb][nb][half * 2 + 0] + bias[col];
                dst[1] = acc[mb][nb][half * 2 + 1] + bias[col + 1];
            }
        }
    }
}

// ================= attention: 256 q rows per CTA, 32 per warp =================
// smem: Q 32K | 3 stages x (K 8K + V 8K) = 80K. 1 CTA/SM.
__global__ __launch_bounds__(256, 1)
void attn_mma(const __half* __restrict__ qh_, const __half* __restrict__ kh_,
              const __half* __restrict__ vh_, __half* __restrict__ Oh)
{
    extern __shared__ __align__(1024) char smem[];
    const uint32_t sb = smem_u32(smem);
    const int qt = gridDim.x - 1 - blockIdx.x;   // longest first
    const int bh = blockIdx.y;
    const int tid = threadIdx.x, wm = tid >> 5, lane = tid & 31;
    const int q0 = qt * 256;
    const size_t gbase = (size_t)bh * TSEQ * HDIM;

    const uint32_t QH = sb;          // 32 KB
    const uint32_t ST = sb + 32768;  // 3 x 16 KB

    auto load_kv = [&](int kt, int s) {
        const int k0 = kt * 64;
        const __half* srcs[2] = {kh_ + gbase + (size_t)k0 * HDIM, vh_ + gbase + (size_t)k0 * HDIM};
        #pragma unroll
        for (int t = 0; t < 2; t++) {
            uint32_t dstb = ST + s * 16384 + t * 8192;
            #pragma unroll
            for (int i = 0; i < 2; i++) {
                int c = tid + i * 256;
                int row = c >> 3, cc = c & 7;
                cp_async16(dstb + swz128(row * 128 + cc * 16), srcs[t] + (size_t)row * HDIM + cc * 8);
            }
        }
    };

    // group 0: Q + kv0; group 1: kv1
    {
        const __half* s0 = qh_ + gbase + (size_t)q0 * HDIM;
        #pragma unroll
        for (int i = 0; i < 8; i++) {
            int c = tid + i * 256;
            int row = c >> 3, cc = c & 7;
            cp_async16(QH + swz128(row * 128 + cc * 16), s0 + (size_t)row * HDIM + cc * 8);
        }
    }
    load_kv(0, 0);
    CP_COMMIT();
    load_kv(1, 1);
    CP_COMMIT();

    float m[2][2], l[2][2];
    #pragma unroll
    for (int mb = 0; mb < 2; mb++)
        #pragma unroll
        for (int g = 0; g < 2; g++) { m[mb][g] = -INFINITY; l[mb][g] = 0.f; }
    float oacc[2][8][4];
    #pragma unroll
    for (int mb = 0; mb < 2; mb++)
        #pragma unroll
        for (int nb = 0; nb < 8; nb++)
            #pragma unroll
            for (int j = 0; j < 4; j++) oacc[mb][nb][j] = 0.f;

    const int r = lane >> 2, tig = lane & 3;
    const int a_row = wm * 32 + (lane & 7) + ((lane >> 3) & 1) * 8;  // + mb*16
    const int a_colb = (lane >> 4) * 16;
    const int b_rowK = (lane & 7) + (lane >> 4) * 8;
    const int b_colbK = ((lane >> 3) & 1) * 16;
    const int v_row = (lane & 7) + ((lane >> 3) & 1) * 8;
    const int v_colb = (lane >> 4) * 16;

    const int nk = 4 * qt + 4;
    for (int kt = 0; kt < nk; kt++) {
        const int st = kt % 3;
        if (kt + 2 < nk)       { load_kv(kt + 2, (kt + 2) % 3); CP_COMMIT(); CP_WAIT(2); }
        else if (kt + 2 == nk) { CP_WAIT(1); }
        else                   { CP_WAIT(0); }
        __syncthreads();
        const int k0 = kt * 64;
        const uint32_t KH = ST + st * 16384, VH = KH + 8192;
        const bool active = (k0 <= q0 + wm * 32 + 31);
        if (active) {
            float sacc[2][8][4];
            #pragma unroll
            for (int mb = 0; mb < 2; mb++)
                #pragma unroll
                for (int nb = 0; nb < 8; nb++)
                    #pragma unroll
                    for (int j = 0; j < 4; j++) sacc[mb][nb][j] = 0.f;
            // ---- S = Q K^T ----
            #pragma unroll
            for (int ks = 0; ks < 4; ks++) {
                uint32_t ah[2][4];
                #pragma unroll
                for (int mb = 0; mb < 2; mb++)
                    ldsm_x4(ah[mb], QH + swz128((a_row + mb * 16) * 128 + a_colb + ks * 32));
                #pragma unroll
                for (int nb16 = 0; nb16 < 4; nb16++) {
                    uint32_t bh4[4];
                    ldsm_x4(bh4, KH + swz128((nb16 * 16 + b_rowK) * 128 + b_colbK + ks * 32));
                    #pragma unroll
                    for (int mb = 0; mb < 2; mb++)
                        #pragma unroll
                        for (int h = 0; h < 2; h++)
                            mma16816h(sacc[mb][nb16 * 2 + h], ah[mb], &bh4[h * 2]);
                }
            }
            // ---- causal mask ----
            #pragma unroll
            for (int mb = 0; mb < 2; mb++) {
                const int qbase = q0 + wm * 32 + mb * 16;
                if (k0 + 63 > qbase) {
                    #pragma unroll
                    for (int nb = 0; nb < 8; nb++)
                        #pragma unroll
                        for (int j = 0; j < 4; j++) {
                            const int qrow = qbase + r + (j >> 1) * 8;
                            const int kcol = k0 + nb * 8 + tig * 2 + (j & 1);
                            if (kcol > qrow) sacc[mb][nb][j] = -INFINITY;
                        }
                }
            }
            // ---- online softmax, exp2 domain, deferred-l ----
            #pragma unroll
            for (int mb = 0; mb < 2; mb++) {
                float rx0 = -INFINITY, rx1 = -INFINITY;
                #pragma unroll
                for (int nb = 0; nb < 8; nb++) {
                    rx0 = fmaxf(rx0, fmaxf(sacc[mb][nb][0], sacc[mb][nb][1]));
                    rx1 = fmaxf(rx1, fmaxf(sacc[mb][nb][2], sacc[mb][nb][3]));
                }
                #pragma unroll
                for (int off = 1; off <= 2; off <<= 1) {
                    rx0 = fmaxf(rx0, __shfl_xor_sync(0xffffffffu, rx0, off));
                    rx1 = fmaxf(rx1, __shfl_xor_sync(0xffffffffu, rx1, off));
                }
                const float nm0 = fmaxf(m[mb][0], rx0), nm1 = fmaxf(m[mb][1], rx1);
                const float sc0 = exp2f(m[mb][0] - nm0), sc1 = exp2f(m[mb][1] - nm1);
                float rs0 = 0.f, rs1 = 0.f;
                #pragma unroll
                for (int nb = 0; nb < 8; nb++) {
                    sacc[mb][nb][0] = exp2f(sacc[mb][nb][0] - nm0);
                    sacc[mb][nb][1] = exp2f(sacc[mb][nb][1] - nm0);
                    sacc[mb][nb][2] = exp2f(sacc[mb][nb][2] - nm1);
                    sacc[mb][nb][3] = exp2f(sacc[mb][nb][3] - nm1);
                    rs0 += sacc[mb][nb][0] + sacc[mb][nb][1];
                    rs1 += sacc[mb][nb][2] + sacc[mb][nb][3];
                }
                l[mb][0] = l[mb][0] * sc0 + rs0;   // per-thread partial
                l[mb][1] = l[mb][1] * sc1 + rs1;
                m[mb][0] = nm0; m[mb][1] = nm1;
                #pragma unroll
                for (int nb = 0; nb < 8; nb++) {
                    oacc[mb][nb][0] *= sc0; oacc[mb][nb][1] *= sc0;
                    oacc[mb][nb][2] *= sc1; oacc[mb][nb][3] *= sc1;
                }
            }
            // ---- O += P V (V frags shared across mb) ----
            #pragma unroll
            for (int j = 0; j < 4; j++) {
                uint32_t pah[2][4];
                #pragma unroll
                for (int mb = 0; mb < 2; mb++) {
                    pah[mb][0] = pack_h(sacc[mb][2 * j][0],     sacc[mb][2 * j][1]);
                    pah[mb][1] = pack_h(sacc[mb][2 * j][2],     sacc[mb][2 * j][3]);
                    pah[mb][2] = pack_h(sacc[mb][2 * j + 1][0], sacc[mb][2 * j + 1][1]);
                    pah[mb][3] = pack_h(sacc[mb][2 * j + 1][2], sacc[mb][2 * j + 1][3]);
                }
                #pragma unroll
                for (int nb16 = 0; nb16 < 4; nb16++) {
                    uint32_t vh4[4];
                    ldsm_x4_t(vh4, VH + swz128((16 * j + v_row) * 128 + nb16 * 32 + v_colb));
                    #pragma unroll
                    for (int mb = 0; mb < 2; mb++)
                        #pragma unroll
                        for (int h = 0; h < 2; h++)
                            mma16816h(oacc[mb][nb16 * 2 + h], pah[mb], &vh4[h * 2]);
                }
            }
        }
        __syncthreads();
    }

    // ---- epilogue: reduce l, write (B,T,C) fp16 ----
    const int b = bh >> 4, h = bh & 15;
    #pragma unroll
    for (int mb = 0; mb < 2; mb++) {
        #pragma unroll
        for (int half = 0; half < 2; half++) {
            float ls = l[mb][half];
            ls += __shfl_xor_sync(0xffffffffu, ls, 1);
            ls += __shfl_xor_sync(0xffffffffu, ls, 2);
            const float inv = 1.0f / ls;
            const int t = q0 + wm * 32 + mb * 16 + r + half * 8;
            const size_t off = ((size_t)(b * TSEQ + t)) * EMBED + h * HDIM;
            #pragma unroll
            for (int nb = 0; nb < 8; nb++) {
                const float v0 = oacc[mb][nb][half * 2 + 0] * inv;
                const float v1 = oacc[mb][nb][half * 2 + 1] * inv;
                *(uint32_t*)(Oh + off + nb * 8 + tig * 2) = pack_h(v0, v1);
            }
        }
    }
}

// ================= launch =================
extern "C" void kernel_launch(void* const* d_in, const int* in_sizes, int n_in,
                              void* d_out, int out_size)
{
    const float* x  = (const float*)d_in[0];
    const float* Wq = (const float*)d_in[1];
    const float* bq = (const float*)d_in[2];
    const float* Wk = (const float*)d_in[3];
    const float* bk = (const float*)d_in[4];
    const float* Wv = (const float*)d_in[5];
    const float* bv = (const float*)d_in[6];
    const float* Wp = (const float*)d_in[7];
    const float* bp = (const float*)d_in[8];
    float* out = (float*)d_out;

    __half *qh, *kh, *vh, *oh, *xh, *wth;
    cudaGetSymbolAddress((void**)&qh, g_qh);
    cudaGetSymbolAddress((void**)&kh, g_kh);
    cudaGetSymbolAddress((void**)&vh, g_vh);
    cudaGetSymbolAddress((void**)&oh, g_oh);
    cudaGetSymbolAddress((void**)&xh, g_xh);
    cudaGetSymbolAddress((void**)&wth, g_wth);

    const int gemm_smem = 3 * STAGE_B;          // 98304
    cudaFuncSetAttribute(qkv_gemm, cudaFuncAttributeMaxDynamicSharedMemorySize, gemm_smem);
    cudaFuncSetAttribute(out_gemm, cudaFuncAttributeMaxDynamicSharedMemorySize, gemm_smem);
    const int attn_smem = 32768 + 3 * 16384;    // 81920
    cudaFuncSetAttribute(attn_mma, cudaFuncAttributeMaxDynamicSharedMemorySize, attn_smem);

    const size_t WN = (size_t)EMBED * EMBED;

    cast_f32h<<<(MROWS * EMBED / 4 + 255) / 256, 256>>>(x, xh, MROWS * EMBED / 4);
    dim3 tgrid(EMBED / 32, EMBED / 32, 4);
    dim3 tblk(32, 8);
    transpose_h4<<<tgrid, tblk>>>(Wq, Wk, Wv, Wp, wth);

    dim3 qkv_grid(24, MROWS / 128);   // (24, 64)
    qkv_gemm<<<qkv_grid, 256, gemm_smem>>>(xh, wth, bq, bk, bv, qh, kh, vh);

    dim3 agrid(TSEQ / 256, BATCH * HEADS);  // (8, 64)
    attn_mma<<<agrid, 256, attn_smem>>>(qh, kh, vh, oh);

    dim3 ogrid(EMBED / 128, MROWS / 128);   // (8, 64)
    out_gemm<<<ogrid, 256, gemm_smem>>>(oh, wth + 3 * WN, bp, out);

    (void)in_sizes; (void)n_in; (void)out_size;
}

// round 10
// speedup vs baseline: 1.0588x; 1.0588x over previous
#include <cuda_runtime.h>
#include <cuda_fp16.h>
#include <math.h>
#include <stdint.h>

#define EMBED   1024
#define HEADS   16
#define HDIM    64
#define BATCH   4
#define TSEQ    2048
#define MROWS   (BATCH * TSEQ)   // 8192

// ================= helpers =================
__device__ __forceinline__ uint32_t smem_u32(const void* p) {
    uint32_t a;
    asm("{ .reg .u64 t; cvta.to.shared.u64 t, %1; cvt.u32.u64 %0, t; }" : "=r"(a) : "l"(p));
    return a;
}
__device__ __forceinline__ uint32_t swz128(uint32_t off) { return off ^ ((off >> 3) & 0x70); }

__device__ __forceinline__ void cp_async16(uint32_t dst, const void* src) {
    asm volatile("cp.async.cg.shared.global [%0], [%1], 16;" :: "r"(dst), "l"(src));
}
#define CP_COMMIT() asm volatile("cp.async.commit_group;" ::: "memory")
#define CP_WAIT(n)  asm volatile("cp.async.wait_group %0;" :: "n"(n) : "memory")

__device__ __forceinline__ void ldsm_x4(uint32_t* r, uint32_t addr) {
    asm volatile("ldmatrix.sync.aligned.m8n8.x4.shared.b16 {%0,%1,%2,%3}, [%4];"
        : "=r"(r[0]), "=r"(r[1]), "=r"(r[2]), "=r"(r[3]) : "r"(addr));
}
__device__ __forceinline__ void ldsm_x4_t(uint32_t* r, uint32_t addr) {
    asm volatile("ldmatrix.sync.aligned.m8n8.x4.trans.shared.b16 {%0,%1,%2,%3}, [%4];"
        : "=r"(r[0]), "=r"(r[1]), "=r"(r[2]), "=r"(r[3]) : "r"(addr));
}
__device__ __forceinline__ void mma16816h(float* d, const uint32_t* a, const uint32_t* b) {
    asm volatile("mma.sync.aligned.m16n8k16.row.col.f32.f16.f16.f32 "
        "{%0,%1,%2,%3}, {%4,%5,%6,%7}, {%8,%9}, {%0,%1,%2,%3};"
        : "+f"(d[0]), "+f"(d[1]), "+f"(d[2]), "+f"(d[3])
        : "r"(a[0]), "r"(a[1]), "r"(a[2]), "r"(a[3]), "r"(b[0]), "r"(b[1]));
}
__device__ __forceinline__ uint32_t pack_h(float x, float y) {
    __half hx = __float2half_rn(x), hy = __float2half_rn(y);
    return (uint32_t)__half_as_ushort(hx) | ((uint32_t)__half_as_ushort(hy) << 16);
}
// fast exp2 via MUFU.EX2
__device__ __forceinline__ float ex2(float x) {
    float y;
    asm("ex2.approx.f32 %0, %1;" : "=f"(y) : "f"(x));
    return y;
}

// ================= scratch (single fp16) =================
__device__ __half g_qh[BATCH * HEADS * TSEQ * HDIM];
__device__ __half g_kh[BATCH * HEADS * TSEQ * HDIM];
__device__ __half g_vh[BATCH * HEADS * TSEQ * HDIM];
__device__ __half g_oh[MROWS * EMBED];
__device__ __half g_xh[MROWS * EMBED];
__device__ __half g_wth[4 * EMBED * EMBED];   // Wt[N,K] per weight

#define QSCALE (0.125f * 1.4426950408889634f)

// ================= cast x -> fp16 =================
__global__ __launch_bounds__(256)
void cast_f32h(const float* __restrict__ in, __half* __restrict__ hi, int n4)
{
    int i = blockIdx.x * blockDim.x + threadIdx.x;
    if (i >= n4) return;
    float4 v = ((const float4*)in)[i];
    ((uint2*)hi)[i] = make_uint2(pack_h(v.x, v.y), pack_h(v.z, v.w));
}

// ================= transpose all 4 weights =================
__global__ __launch_bounds__(256)
void transpose_h4(const float* __restrict__ W0, const float* __restrict__ W1,
                  const float* __restrict__ W2, const float* __restrict__ W3,
                  __half* __restrict__ hi)
{
    __shared__ float t[32][33];
    const int z = blockIdx.z;
    const float* W = (z == 0) ? W0 : (z == 1) ? W1 : (z == 2) ? W2 : W3;
    __half* dst = hi + (size_t)z * EMBED * EMBED;
    const int bx = blockIdx.x * 32;
    const int by = blockIdx.y * 32;
    const int x = threadIdx.x, y = threadIdx.y;
    #pragma unroll
    for (int j = 0; j < 32; j += 8)
        t[y + j][x] = W[(size_t)(by + y + j) * EMBED + bx + x];
    __syncthreads();
    #pragma unroll
    for (int j = 0; j < 32; j += 8)
        dst[(size_t)(bx + y + j) * EMBED + by + x] = __float2half_rn(t[x][y + j]);
}

// ================= single-fp16 HMMA GEMM (3-stage) =================
#define TILE_B  16384     // 128 rows x 64 fp16 x 2B
#define STAGE_B 32768     // 2 tiles: Ah, Bh

__global__ __launch_bounds__(256, 2)
void qkv_gemm(const __half* __restrict__ Ah_, const __half* __restrict__ Wh,
              const float* __restrict__ bq, const float* __restrict__ bk, const float* __restrict__ bv,
              __half* __restrict__ qh, __half* __restrict__ kh, __half* __restrict__ vh)
{
    constexpr int K = EMBED, NK = 16;
    extern __shared__ __align__(1024) char smem[];
    const uint32_t sb = smem_u32(smem);
    const int tid = threadIdx.x, wid = tid >> 5, lane = tid & 31;
    const int widx = blockIdx.x >> 3;
    const int n0 = (blockIdx.x & 7) * 128, m0 = blockIdx.y * 128;
    const size_t WN = (size_t)EMBED * EMBED;

    const __half* Bh = Wh + (size_t)widx * WN;
    const float* bias = (widx == 0) ? bq : (widx == 1) ? bk : bv;
    __half* Cdst = (widx == 0) ? qh : (widx == 1) ? kh : vh;
    const float scale = (widx == 0) ? QSCALE : 1.0f;

    const int warp_m = wid & 3, warp_n = wid >> 2;
    float acc[2][8][4];
    #pragma unroll
    for (int mb = 0; mb < 2; mb++)
        #pragma unroll
        for (int nb = 0; nb < 8; nb++)
            #pragma unroll
            for (int j = 0; j < 4; j++) acc[mb][nb][j] = 0.f;

    const int a_row = warp_m * 32 + (lane & 7) + ((lane >> 3) & 1) * 8;
    const int a_col = (lane >> 4) * 16;
    const int b_row = warp_n * 64 + (lane & 7) + (lane >> 4) * 8;
    const int b_col = ((lane >> 3) & 1) * 16;

    const __half* srcs[2] = {Ah_, Bh};

    auto load_chunk = [&](int kt, int s) {
        #pragma unroll
        for (int t = 0; t < 2; t++) {
            const __half* base = srcs[t] + (size_t)((t == 0) ? m0 : n0) * K + kt * 64;
            const uint32_t tb = sb + s * STAGE_B + t * TILE_B;
            #pragma unroll
            for (int i = 0; i < 4; i++) {
                int chunk = tid + i * 256;
                int r = chunk >> 3, c = chunk & 7;
                cp_async16(tb + swz128(r * 128 + c * 16), base + (size_t)r * K + c * 8);
            }
        }
        CP_COMMIT();
    };

    load_chunk(0, 0);
    load_chunk(1, 1);
    for (int kt = 0; kt < NK; kt++) {
        const int st = kt % 3;
        if (kt + 2 < NK)       { load_chunk(kt + 2, (kt + 2) % 3); CP_WAIT(2); }
        else if (kt + 2 == NK) { CP_WAIT(1); }
        else                   { CP_WAIT(0); }
        __syncthreads();
        const uint32_t tAh = sb + st * STAGE_B, tBh = tAh + TILE_B;
        #pragma unroll
        for (int ks = 0; ks < 4; ks++) {
            uint32_t ah[2][4], bh4[4][4];
            #pragma unroll
            for (int mb = 0; mb < 2; mb++)
                ldsm_x4(ah[mb], tAh + swz128((a_row + mb * 16) * 128 + a_col + ks * 32));
            #pragma unroll
            for (int nb = 0; nb < 4; nb++)
                ldsm_x4(bh4[nb], tBh + swz128((b_row + nb * 16) * 128 + b_col + ks * 32));
            #pragma unroll
            for (int mb = 0; mb < 2; mb++)
                #pragma unroll
                for (int nb = 0; nb < 4; nb++)
                    #pragma unroll
                    for (int h = 0; h < 2; h++)
                        mma16816h(acc[mb][nb * 2 + h], ah[mb], &bh4[nb][h * 2]);
        }
        __syncthreads();
    }

    const int er = m0 + warp_m * 32 + (lane >> 2);
    const int ec = n0 + warp_n * 64 + (lane & 3) * 2;
    #pragma unroll
    for (int mb = 0; mb < 2; mb++) {
        #pragma unroll
        for (int half = 0; half < 2; half++) {
            const int row = er + mb * 16 + half * 8;
            const int b = row / TSEQ, t = row % TSEQ;
            #pragma unroll
            for (int nb = 0; nb < 8; nb++) {
                const int col = ec + nb * 8;
                const float v0 = (acc[mb][nb][half * 2 + 0] + bias[col]) * scale;
                const float v1 = (acc[mb][nb][half * 2 + 1] + bias[col + 1]) * scale;
                const int hh = col >> 6, dd = col & 63;
                const size_t idx = (((size_t)(b * HEADS + hh)) * TSEQ + t) * HDIM + dd;
                *(uint32_t*)(Cdst + idx) = pack_h(v0, v1);
            }
        }
    }
}

__global__ __launch_bounds__(256, 2)
void out_gemm(const __half* __restrict__ Ah_, const __half* __restrict__ Bh_,
              const float* __restrict__ bias, float* __restrict__ Cf)
{
    constexpr int K = EMBED, NG = EMBED, NK = 16;
    extern __shared__ __align__(1024) char smem[];
    const uint32_t sb = smem_u32(smem);
    const int tid = threadIdx.x, wid = tid >> 5, lane = tid & 31;
    const int n0 = blockIdx.x * 128, m0 = blockIdx.y * 128;

    const int warp_m = wid & 3, warp_n = wid >> 2;
    float acc[2][8][4];
    #pragma unroll
    for (int mb = 0; mb < 2; mb++)
        #pragma unroll
        for (int nb = 0; nb < 8; nb++)
            #pragma unroll
            for (int j = 0; j < 4; j++) acc[mb][nb][j] = 0.f;

    const int a_row = warp_m * 32 + (lane & 7) + ((lane >> 3) & 1) * 8;
    const int a_col = (lane >> 4) * 16;
    const int b_row = warp_n * 64 + (lane & 7) + (lane >> 4) * 8;
    const int b_col = ((lane >> 3) & 1) * 16;

    const __half* srcs[2] = {Ah_, Bh_};

    auto load_chunk = [&](int kt, int s) {
        #pragma unroll
        for (int t = 0; t < 2; t++) {
            const __half* base = srcs[t] + (size_t)((t == 0) ? m0 : n0) * K + kt * 64;
            const uint32_t tb = sb + s * STAGE_B + t * TILE_B;
            #pragma unroll
            for (int i = 0; i < 4; i++) {
                int chunk = tid + i * 256;
                int r = chunk >> 3, c = chunk & 7;
                cp_async16(tb + swz128(r * 128 + c * 16), base + (size_t)r * K + c * 8);
            }
        }
        CP_COMMIT();
    };

    load_chunk(0, 0);
    load_chunk(1, 1);
    for (int kt = 0; kt < NK; kt++) {
        const int st = kt % 3;
        if (kt + 2 < NK)       { load_chunk(kt + 2, (kt + 2) % 3); CP_WAIT(2); }
        else if (kt + 2 == NK) { CP_WAIT(1); }
        else                   { CP_WAIT(0); }
        __syncthreads();
        const uint32_t tAh = sb + st * STAGE_B, tBh = tAh + TILE_B;
        #pragma unroll
        for (int ks = 0; ks < 4; ks++) {
            uint32_t ah[2][4], bh4[4][4];
            #pragma unroll
            for (int mb = 0; mb < 2; mb++)
                ldsm_x4(ah[mb], tAh + swz128((a_row + mb * 16) * 128 + a_col + ks * 32));
            #pragma unroll
            for (int nb = 0; nb < 4; nb++)
                ldsm_x4(bh4[nb], tBh + swz128((b_row + nb * 16) * 128 + b_col + ks * 32));
            #pragma unroll
            for (int mb = 0; mb < 2; mb++)
                #pragma unroll
                for (int nb = 0; nb < 4; nb++)
                    #pragma unroll
                    for (int h = 0; h < 2; h++)
                        mma16816h(acc[mb][nb * 2 + h], ah[mb], &bh4[nb][h * 2]);
        }
        __syncthreads();
    }

    const int er = m0 + warp_m * 32 + (lane >> 2);
    const int ec = n0 + warp_n * 64 + (lane & 3) * 2;
    #pragma unroll
    for (int mb = 0; mb < 2; mb++) {
        #pragma unroll
        for (int half = 0; half < 2; half++) {
            const int row = er + mb * 16 + half * 8;
            #pragma unroll
            for (int nb = 0; nb < 8; nb++) {
                const int col = ec + nb * 8;
                float* dst = Cf + (size_t)row * NG + col;
                dst[0] = acc[mb][nb][half * 2 + 0] + bias[col];
                dst[1] = acc[mb][nb][half * 2 + 1] + bias[col + 1];
            }
        }
    }
}

// ================= attention: R8 geometry + ex2.approx + deferred-l =================
// 128 q rows / CTA, 16 per warp; smem: Q 16K | 3 x (K 8K + V 8K) = 64K; 2 CTAs/SM.
__global__ __launch_bounds__(256, 2)
void attn_mma(const __half* __restrict__ qh_, const __half* __restrict__ kh_,
              const __half* __restrict__ vh_, __half* __restrict__ Oh)
{
    extern __shared__ __align__(1024) char smem[];
    const uint32_t sb = smem_u32(smem);
    const int qt = gridDim.x - 1 - blockIdx.x;   // longest tiles first
    const int bh = blockIdx.y;
    const int tid = threadIdx.x, wm = tid >> 5, lane = tid & 31;
    const int q0 = qt * 128;
    const size_t gbase = (size_t)bh * TSEQ * HDIM;

    const uint32_t QH = sb;
    const uint32_t ST = sb + 16384;   // 3 stages x 16K

    {
        const __half* s0 = qh_ + gbase + (size_t)q0 * HDIM;
        #pragma unroll
        for (int i = 0; i < 4; i++) {
            int c = tid + i * 256;
            int row = c >> 3, cc = c & 7;
            cp_async16(QH + swz128(row * 128 + cc * 16), s0 + (size_t)row * HDIM + cc * 8);
        }
    }
    auto load_kv = [&](int kt, int s) {
        const int k0 = kt * 64;
        const __half* srcs[2] = {kh_ + gbase + (size_t)k0 * HDIM, vh_ + gbase + (size_t)k0 * HDIM};
        #pragma unroll
        for (int t = 0; t < 2; t++) {
            uint32_t dstb = ST + s * 16384 + t * 8192;
            #pragma unroll
            for (int i = 0; i < 2; i++) {
                int c = tid + i * 256;
                int row = c >> 3, cc = c & 7;
                cp_async16(dstb + swz128(row * 128 + cc * 16), srcs[t] + (size_t)row * HDIM + cc * 8);
            }
        }
    };
    load_kv(0, 0);
    CP_COMMIT();
    load_kv(1, 1);
    CP_COMMIT();

    float m0 = -INFINITY, m1 = -INFINITY, l0 = 0.f, l1 = 0.f;
    float oacc[8][4];
    #pragma unroll
    for (int nb = 0; nb < 8; nb++)
        #pragma unroll
        for (int j = 0; j < 4; j++) oacc[nb][j] = 0.f;

    const int r = lane >> 2, tig = lane & 3;
    const int a_row = wm * 16 + (lane & 7) + ((lane >> 3) & 1) * 8;
    const int a_colb = (lane >> 4) * 16;
    const int b_rowK = (lane & 7) + (lane >> 4) * 8;
    const int b_colbK = ((lane >> 3) & 1) * 16;
    const int v_row = (lane & 7) + ((lane >> 3) & 1) * 8;
    const int v_colb = (lane >> 4) * 16;

    const int nk = 2 * qt + 2;
    for (int kt = 0; kt < nk; kt++) {
        const int st = kt % 3;
        if (kt + 2 < nk)       { load_kv(kt + 2, (kt + 2) % 3); CP_COMMIT(); CP_WAIT(2); }
        else if (kt + 2 == nk) { CP_WAIT(1); }
        else                   { CP_WAIT(0); }
        __syncthreads();
        const int k0 = kt * 64;
        const uint32_t KH = ST + st * 16384, VH = KH + 8192;
        const bool active = (k0 <= q0 + wm * 16 + 15);
        if (active) {
            float sacc[8][4];
            #pragma unroll
            for (int nb = 0; nb < 8; nb++)
                #pragma unroll
                for (int j = 0; j < 4; j++) sacc[nb][j] = 0.f;
            #pragma unroll
            for (int ks = 0; ks < 4; ks++) {
                uint32_t ah[4];
                ldsm_x4(ah, QH + swz128(a_row * 128 + a_colb + ks * 32));
                #pragma unroll
                for (int nb16 = 0; nb16 < 4; nb16++) {
                    uint32_t bh4[4];
                    ldsm_x4(bh4, KH + swz128((nb16 * 16 + b_rowK) * 128 + b_colbK + ks * 32));
                    #pragma unroll
                    for (int h = 0; h < 2; h++)
                        mma16816h(sacc[nb16 * 2 + h], ah, &bh4[h * 2]);
                }
            }
            if (k0 + 63 > q0 + wm * 16) {
                #pragma unroll
                for (int nb = 0; nb < 8; nb++)
                    #pragma unroll
                    for (int j = 0; j < 4; j++) {
                        const int qrow = q0 + wm * 16 + r + (j >> 1) * 8;
                        const int kcol = k0 + nb * 8 + tig * 2 + (j & 1);
                        if (kcol > qrow) sacc[nb][j] = -INFINITY;
                    }
            }
            // online softmax (exp2 domain, MUFU.EX2, deferred-l)
            float rx0 = -INFINITY, rx1 = -INFINITY;
            #pragma unroll
            for (int nb = 0; nb < 8; nb++) {
                rx0 = fmaxf(rx0, fmaxf(sacc[nb][0], sacc[nb][1]));
                rx1 = fmaxf(rx1, fmaxf(sacc[nb][2], sacc[nb][3]));
            }
            #pragma unroll
            for (int off = 1; off <= 2; off <<= 1) {
                rx0 = fmaxf(rx0, __shfl_xor_sync(0xffffffffu, rx0, off));
                rx1 = fmaxf(rx1, __shfl_xor_sync(0xffffffffu, rx1, off));
            }
            const float nm0 = fmaxf(m0, rx0), nm1 = fmaxf(m1, rx1);
            const float sc0 = ex2(m0 - nm0), sc1 = ex2(m1 - nm1);
            float rs0 = 0.f, rs1 = 0.f;
            #pragma unroll
            for (int nb = 0; nb < 8; nb++) {
                sacc[nb][0] = ex2(sacc[nb][0] - nm0);
                sacc[nb][1] = ex2(sacc[nb][1] - nm0);
                sacc[nb][2] = ex2(sacc[nb][2] - nm1);
                sacc[nb][3] = ex2(sacc[nb][3] - nm1);
                rs0 += sacc[nb][0] + sacc[nb][1];
                rs1 += sacc[nb][2] + sacc[nb][3];
            }
            l0 = l0 * sc0 + rs0;   // per-thread partial; reduced in epilogue
            l1 = l1 * sc1 + rs1;
            m0 = nm0; m1 = nm1;
            #pragma unroll
            for (int nb = 0; nb < 8; nb++) {
                oacc[nb][0] *= sc0; oacc[nb][1] *= sc0;
                oacc[nb][2] *= sc1; oacc[nb][3] *= sc1;
            }
            #pragma unroll
            for (int j = 0; j < 4; j++) {
                uint32_t pah[4];
                pah[0] = pack_h(sacc[2 * j][0],     sacc[2 * j][1]);
                pah[1] = pack_h(sacc[2 * j][2],     sacc[2 * j][3]);
                pah[2] = pack_h(sacc[2 * j + 1][0], sacc[2 * j + 1][1]);
                pah[3] = pack_h(sacc[2 * j + 1][2], sacc[2 * j + 1][3]);
                #pragma unroll
                for (int nb16 = 0; nb16 < 4; nb16++) {
                    uint32_t vh4[4];
                    ldsm_x4_t(vh4, VH + swz128((16 * j + v_row) * 128 + nb16 * 32 + v_colb));
                    #pragma unroll
                    for (int h = 0; h < 2; h++)
                        mma16816h(oacc[nb16 * 2 + h], pah, &vh4[h * 2]);
                }
            }
        }
        __syncthreads();
    }

    // epilogue: reduce l across the 4-lane row group, then write
    l0 += __shfl_xor_sync(0xffffffffu, l0, 1);
    l0 += __shfl_xor_sync(0xffffffffu, l0, 2);
    l1 += __shfl_xor_sync(0xffffffffu, l1, 1);
    l1 += __shfl_xor_sync(0xffffffffu, l1, 2);
    const float inv0 = 1.0f / l0, inv1 = 1.0f / l1;
    const int b = bh >> 4, h = bh & 15;
    #pragma unroll
    for (int half = 0; half < 2; half++) {
        const int t = q0 + wm * 16 + r + half * 8;
        const float inv = half ? inv1 : inv0;
        const size_t off = ((size_t)(b * TSEQ + t)) * EMBED + h * HDIM;
        #pragma unroll
        for (int nb = 0; nb < 8; nb++) {
            const float v0 = oacc[nb][half * 2 + 0] * inv;
            const float v1 = oacc[nb][half * 2 + 1] * inv;
            *(uint32_t*)(Oh + off + nb * 8 + tig * 2) = pack_h(v0, v1);
        }
    }
}

// ================= launch =================
extern "C" void kernel_launch(void* const* d_in, const int* in_sizes, int n_in,
                              void* d_out, int out_size)
{
    const float* x  = (const float*)d_in[0];
    const float* Wq = (const float*)d_in[1];
    const float* bq = (const float*)d_in[2];
    const float* Wk = (const float*)d_in[3];
    const float* bk = (const float*)d_in[4];
    const float* Wv = (const float*)d_in[5];
    const float* bv = (const float*)d_in[6];
    const float* Wp = (const float*)d_in[7];
    const float* bp = (const float*)d_in[8];
    float* out = (float*)d_out;

    __half *qh, *kh, *vh, *oh, *xh, *wth;
    cudaGetSymbolAddress((void**)&qh, g_qh);
    cudaGetSymbolAddress((void**)&kh, g_kh);
    cudaGetSymbolAddress((void**)&vh, g_vh);
    cudaGetSymbolAddress((void**)&oh, g_oh);
    cudaGetSymbolAddress((void**)&xh, g_xh);
    cudaGetSymbolAddress((void**)&wth, g_wth);

    const int gemm_smem = 3 * STAGE_B;          // 98304
    cudaFuncSetAttribute(qkv_gemm, cudaFuncAttributeMaxDynamicSharedMemorySize, gemm_smem);
    cudaFuncSetAttribute(out_gemm, cudaFuncAttributeMaxDynamicSharedMemorySize, gemm_smem);
    const int attn_smem = 16384 + 3 * 16384;    // 65536
    cudaFuncSetAttribute(attn_mma, cudaFuncAttributeMaxDynamicSharedMemorySize, attn_smem);

    const size_t WN = (size_t)EMBED * EMBED;

    cast_f32h<<<(MROWS * EMBED / 4 + 255) / 256, 256>>>(x, xh, MROWS * EMBED / 4);
    dim3 tgrid(EMBED / 32, EMBED / 32, 4);
    dim3 tblk(32, 8);
    transpose_h4<<<tgrid, tblk>>>(Wq, Wk, Wv, Wp, wth);

    dim3 qkv_grid(24, MROWS / 128);   // (24, 64)
    qkv_gemm<<<qkv_grid, 256, gemm_smem>>>(xh, wth, bq, bk, bv, qh, kh, vh);

    dim3 agrid(TSEQ / 128, BATCH * HEADS);  // (16, 64)
    attn_mma<<<agrid, 256, attn_smem>>>(qh, kh, vh, oh);

    dim3 ogrid(EMBED / 128, MROWS / 128);   // (8, 64)
    out_gemm<<<ogrid, 256, gemm_smem>>>(oh, wth + 3 * WN, bp, out);

    (void)in_sizes; (void)n_in; (void)out_size;
}